// round 15
// baseline (speedup 1.0000x reference)
#include <cuda_runtime.h>
#include <cuda_fp16.h>
#include <math.h>
#include <stdint.h>

#define B_    128
#define L_    512
#define D_    128
#define H_    8
#define E_    16
#define DFF_  512
#define LP_   514

// ---------------- fp32 scratch ----------------
__device__ float g_T2 [B_*L_*D_];
__device__ float g_F  [B_*D_*128];
__device__ float g_PE [512*128];
__device__ float g_CM [B_*D_];

// ---------------- fp16 scratch ----------------
__device__ __half g_MarkH[B_*L_*D_];
__device__ __half g_X [B_*LP_*D_];
__device__ __half g_Hx[B_*L_*D_];
__device__ __half g_HT[B_*L_*D_];      // H transposed (b,d,l)
__device__ __half g_GT[B_*D_*128];     // DFT(H) transposed: [(b,n),k]
__device__ __half g_Q [B_*L_*D_];      // iDFT out flat
__device__ __half g_S [B_*D_*128];
__device__ __half g_U [B_*L_*DFF_];
__device__ __half g_HN[B_*L_*D_];

// ---------------- fp16 weights ----------------
__device__ __half g_cw[128*384];
__device__ __half g_fb[128*512];
__device__ __half g_ib[512*128];
__device__ __half g_wq[2*128*128];
__device__ __half g_wo[2*128*128];
__device__ __half g_w1[2*512*128];
__device__ __half g_w2[2*128*512];

__device__ __forceinline__ float geluf(float v) {
    return 0.5f * v * (1.0f + erff(v * 0.7071067811865476f));
}
__device__ __forceinline__ uint32_t pack2h(__half a, __half b) {
    return (uint32_t)__half_as_ushort(a) | ((uint32_t)__half_as_ushort(b) << 16);
}
__device__ __forceinline__ uint32_t smem_u32(const void* p) {
    uint32_t a;
    asm("{ .reg .u64 t; cvta.to.shared.u64 t, %1; cvt.u32.u64 %0, t; }" : "=r"(a) : "l"(p));
    return a;
}
__device__ __forceinline__ void ldsm4(uint32_t* r, uint32_t a) {
    asm volatile("ldmatrix.sync.aligned.m8n8.x4.shared.b16 {%0,%1,%2,%3}, [%4];"
        : "=r"(r[0]), "=r"(r[1]), "=r"(r[2]), "=r"(r[3]) : "r"(a));
}
__device__ __forceinline__ void mma16816(float* c, const uint32_t* a, const uint32_t* b) {
    asm volatile(
        "mma.sync.aligned.m16n8k16.row.col.f32.f16.f16.f32 "
        "{%0,%1,%2,%3}, {%4,%5,%6,%7}, {%8,%9}, {%0,%1,%2,%3};"
        : "+f"(c[0]), "+f"(c[1]), "+f"(c[2]), "+f"(c[3])
        : "r"(a[0]), "r"(a[1]), "r"(a[2]), "r"(a[3]), "r"(b[0]), "r"(b[1]));
}
#define CP16(d, s)   asm volatile("cp.async.cg.shared.global [%0], [%1], 16;" :: "r"(d), "l"(s))
#define CPCOMMIT()   asm volatile("cp.async.commit_group;" ::: "memory")
#define CPWAIT2()    asm volatile("cp.async.wait_group 2;" ::: "memory")

__device__ __forceinline__ uint32_t sw32(int row, int ch) {
    return (uint32_t)(row * 64) + (uint32_t)(((ch ^ ((row >> 1) & 3)) << 4));
}

// ---------------- prep ----------------
__global__ void k_prep(const float* __restrict__ conv_w, const float* __restrict__ Wq,
                       const float* __restrict__ Wo, const float* __restrict__ W1,
                       const float* __restrict__ W2, const float* __restrict__ pb,
                       float* __restrict__ out) {
    int idx = blockIdx.x * 256 + threadIdx.x;   // 65536 total
    if (idx < 49152) {
        int n = idx / 384, k = idx - n*384;
        int s = k >> 7, din = k & 127;
        g_cw[idx] = __float2half_rn(conv_w[n*384 + din*3 + s]);
    }
    if (idx < B_*D_) g_CM[idx] = 0.f;
    if (idx < B_)    out[idx] = pb[0];
    {   // forward DFT basis: N=128 (coeff), K=512 (t)
        int n = idx >> 9, t = idx & 511, m = n & 63;
        float x = (float)(m * t) * (1.0f/256.0f);
        float v = (n < 64) ? cospif(x) : -sinpif(x);
        g_fb[idx] = __float2half_rn(v);
    }
    {   // inverse DFT basis: N=512 (t), K=128 (coeff)
        int t = idx >> 7, n = idx & 127, m = n & 63;
        float x = (float)(m * t) * (1.0f/256.0f);
        float v;
        if (n == 0)       v = 1.0f/512.0f;
        else if (n < 64)  v = cospif(x) * (2.0f/512.0f);
        else if (n == 64) v = 0.0f;
        else              v = -sinpif(x) * (2.0f/512.0f);
        g_ib[idx] = __float2half_rn(v);
    }
    #pragma unroll
    for (int ly = 0; ly < 2; ly++) {
        if (idx < 16384) {
            int n = idx >> 7, k = idx & 127;
            g_wq[ly*16384 + idx] = __float2half_rn(Wq[ly*16384 + k*128 + n]);
            g_wo[ly*16384 + idx] = __float2half_rn(Wo[ly*16384 + k*128 + n]);
        }
        {
            int n = idx >> 7, k = idx & 127;
            g_w1[ly*65536 + idx] = __float2half_rn(W1[ly*65536 + k*512 + n]);
        }
        {
            int n = idx >> 9, k = idx & 511;
            g_w2[ly*65536 + idx] = __float2half_rn(W2[ly*65536 + k*128 + n]);
        }
    }
    {
        int t = idx >> 7, d = idx & 127;
        int i2 = d & ~1;
        float div = expf((float)i2 * (-9.210340371976184f / 128.0f));
        float a = (float)t * div;
        g_PE[idx] = (d & 1) ? cosf(a) : sinf(a);
    }
}

// ---------------- input transpose + circular edges -------------------------
__global__ void k_transpose(const float* __restrict__ x_enc,
                            const float* __restrict__ mark) {
    __shared__ float tile [32][33];
    __shared__ float tileM[32][33];
    int b = blockIdx.z;
    int d0 = blockIdx.y * 32, l0 = blockIdx.x * 32;
    int tx = threadIdx.x, ty = threadIdx.y;
    const float* xb = x_enc + b*65536;
    const float* mb = mark  + b*65536;
    #pragma unroll
    for (int i = ty; i < 32; i += 8) {
        tile [i][tx] = xb[(d0+i)*512 + l0 + tx];
        tileM[i][tx] = mb[(d0+i)*512 + l0 + tx];
    }
    __syncthreads();
    #pragma unroll
    for (int i = ty; i < 32; i += 8) {
        int oi = b*LP_*128 + (l0+i+1)*128 + d0+tx;
        g_X[oi] = __float2half_rn(tile[tx][i]);
        g_MarkH[b*65536 + (l0+i)*128 + d0+tx] = __float2half_rn(tileM[tx][i]);
    }
    if (ty == 0) {
        if (blockIdx.x == 0)
            g_X[b*LP_*128 + 513*128 + d0+tx] = __float2half_rn(tile[tx][0]);
        if (blockIdx.x == 15)
            g_X[b*LP_*128 + d0+tx] = __float2half_rn(tile[tx][31]);
    }
}

// ---------------- fp16 HMMA GEMM, cp.async 4-stage, K-chunk 32 --------------
// CTA tile 64(M) x 128(N); 8 warps of 32x32; 4 CTAs/SM.
// EPI bits: 1=+bias, 2=+res(fp16), 4=gelu, 8=+PE, 16=skip fp32 C store
// WRB: write fp16 to Cf (flat, ldc).
// WRT=1: fp16 staged transpose -> Ct, batches of 512 rows, dest stride 512.
// WRT=3: fp16 staged transpose -> Ct, batches of 128 rows, dest stride 128.
// WRT=2: fp32 staged transpose -> C,  batches of 128 rows, dest stride 128.
template<int EPI, int WRB, int WRT>
__global__ void __launch_bounds__(256, 4) k_tgemm(
    const __half* __restrict__ A, const __half* __restrict__ B,
    const float* __restrict__ bias, const __half* __restrict__ res,
    float* __restrict__ C, __half* __restrict__ Cf, __half* __restrict__ Ct,
    int K, int ldc, int absh, int abstr, int arstr)
{
    extern __shared__ char sm[];
    const uint32_t sU = smem_u32(sm);
    const int tid = threadIdx.x, wid = tid >> 5, lane = tid & 31;
    const int rowBase = blockIdx.x * 64, colBase = blockIdx.y * 128;
    const int amask = (1 << absh) - 1;

    float acc[2][4][4];
    #pragma unroll
    for (int i = 0; i < 2; i++)
        #pragma unroll
        for (int j = 0; j < 4; j++)
            #pragma unroll
            for (int q = 0; q < 4; q++) acc[i][j][q] = 0.f;

    const int nc = K >> 5;

    const int a_row = tid >> 2, a_ch = tid & 3;
    const uint32_t a_sw = sw32(a_row, a_ch);
    int a_rg = rowBase + a_row;
    const long a_base = (long)(a_rg >> absh)*abstr + (long)(a_rg & amask)*arstr + a_ch*8;
    const int b_row0 = tid >> 2, b_row1 = 64 + (tid >> 2);
    const uint32_t b_sw0 = sw32(b_row0, a_ch), b_sw1 = sw32(b_row1, a_ch);
    const long b_base0 = (long)(colBase + b_row0)*K + a_ch*8;
    const long b_base1 = (long)(colBase + b_row1)*K + a_ch*8;

    auto load_chunk = [&](int stage, int k0) {
        uint32_t sb = sU + stage * 12288;
        CP16(sb +        a_sw, A + a_base + k0);
        CP16(sb + 4096 + b_sw0, B + b_base0 + k0);
        CP16(sb + 4096 + b_sw1, B + b_base1 + k0);
    };

    load_chunk(0, 0);  CPCOMMIT();
    load_chunk(1, 32); CPCOMMIT();
    load_chunk(2, 64); CPCOMMIT();

    const int mrow = (wid & 1) * 32;
    const int ncol = (wid >> 1) * 32;
    const int a_lr  = mrow + (lane & 15);
    const int a_lc  = lane >> 4;
    const int b_lr  = ncol + (lane & 7) + ((lane & 16) ? 8 : 0);
    const int b_lc  = (lane >> 3) & 1;
    int stage = 0;

    for (int c = 0; c < nc; c++) {
        CPWAIT2();
        __syncthreads();
        if (c + 3 < nc) load_chunk((stage + 3) & 3, (c + 3) * 32);
        CPCOMMIT();

        uint32_t sb = sU + stage * 12288;
        #pragma unroll
        for (int ks = 0; ks < 2; ks++) {
            uint32_t af[2][4], bf[2][4];
            #pragma unroll
            for (int g = 0; g < 2; g++) {
                int r = b_lr + g*16, ci = ks*2 + b_lc;
                ldsm4(bf[g], sb + 4096 + sw32(r, ci));
            }
            #pragma unroll
            for (int f = 0; f < 2; f++) {
                int r = a_lr + f*16, ci = ks*2 + a_lc;
                ldsm4(af[f], sb + sw32(r, ci));
            }
            #pragma unroll
            for (int mi = 0; mi < 2; mi++)
                #pragma unroll
                for (int ni = 0; ni < 4; ni++)
                    mma16816(acc[mi][ni], af[mi], &bf[ni >> 1][(ni & 1) * 2]);
        }
        stage = (stage + 1) & 3;
    }

    if (WRT) __syncthreads();
    __half* tst  = (__half*)(sm + wid * 2176);   // 32x33 halves
    float* tst32 = (float*)(sm + wid * 4224);    // 32x33 floats

    // ---- epilogue ----
    #pragma unroll
    for (int mi = 0; mi < 2; mi++) {
        #pragma unroll
        for (int half = 0; half < 2; half++) {
            int grow = rowBase + mrow + mi*16 + (lane >> 2) + half*8;
            #pragma unroll
            for (int ni = 0; ni < 4; ni++) {
                int gcol = colBase + ncol + ni*8 + (lane & 3)*2;
                float v0 = acc[mi][ni][half*2 + 0];
                float v1 = acc[mi][ni][half*2 + 1];
                if (EPI & 1) { v0 += bias[gcol]; v1 += bias[gcol + 1]; }
                if (EPI & 8) {
                    int pbi = (grow & 511)*128 + (gcol & 127);
                    v0 += g_PE[pbi]; v1 += g_PE[pbi + 1];
                }
                long oidx = (long)grow * ldc + gcol;
                if (EPI & 2) {
                    __half2 rr = *(const __half2*)(res + oidx);
                    v0 += __low2float(rr); v1 += __high2float(rr);
                }
                if (EPI & 4) { v0 = geluf(v0); v1 = geluf(v1); }
                if (!(EPI & 16)) {
                    float2 o; o.x = v0; o.y = v1;
                    *(float2*)(C + oidx) = o;
                }
                if (WRB) {
                    *(uint32_t*)(Cf + oidx) =
                        pack2h(__float2half_rn(v0), __float2half_rn(v1));
                }
                if (WRT == 2) {
                    int cl = ni*8 + (lane & 3)*2;
                    int rl = mi*16 + (lane >> 2) + half*8;
                    tst32[cl*33 + rl]     = v0;
                    tst32[(cl+1)*33 + rl] = v1;
                } else if (WRT) {
                    int cl = ni*8 + (lane & 3)*2;
                    int rl = mi*16 + (lane >> 2) + half*8;
                    tst[cl*33 + rl]     = __float2half_rn(v0);
                    tst[(cl+1)*33 + rl] = __float2half_rn(v1);
                }
            }
        }
    }
    if (WRT == 1) {
        __syncwarp();
        int bI = rowBase >> 9;
        int tb = (rowBase & 511) + mrow + (lane & 7)*4;
        #pragma unroll
        for (int rep = 0; rep < 8; rep++) {
            int dl = rep*4 + (lane >> 3);
            int tl = (lane & 7)*4;
            uint2 o;
            o.x = pack2h(tst[dl*33 + tl],     tst[dl*33 + tl + 1]);
            o.y = pack2h(tst[dl*33 + tl + 2], tst[dl*33 + tl + 3]);
            int dg = (ncol + dl) & 127;
            *(uint2*)(Ct + bI*65536 + dg*512 + tb) = o;
        }
    }
    if (WRT == 3) {
        __syncwarp();
        int bI = rowBase >> 7;
        int tb = (rowBase & 127) + mrow + (lane & 7)*4;
        #pragma unroll
        for (int rep = 0; rep < 8; rep++) {
            int dl = rep*4 + (lane >> 3);
            int tl = (lane & 7)*4;
            uint2 o;
            o.x = pack2h(tst[dl*33 + tl],     tst[dl*33 + tl + 1]);
            o.y = pack2h(tst[dl*33 + tl + 2], tst[dl*33 + tl + 3]);
            *(uint2*)(Ct + bI*16384 + (ncol + dl)*128 + tb) = o;
        }
    }
    if (WRT == 2) {
        __syncwarp();
        int bI = rowBase >> 7;
        int tb = (rowBase & 127) + mrow + (lane & 7)*4;
        #pragma unroll
        for (int rep = 0; rep < 8; rep++) {
            int dl = rep*4 + (lane >> 3);
            int tl = (lane & 7)*4;
            float4 o;
            o.x = tst32[dl*33 + tl];     o.y = tst32[dl*33 + tl + 1];
            o.z = tst32[dl*33 + tl + 2]; o.w = tst32[dl*33 + tl + 3];
            *(float4*)(C + bI*16384 + (ncol + dl)*128 + tb) = o;
        }
    }
}

// ---------------- complex mode mixing (fp32 in, fp16 out) ------------------
// bias folded: F_re[m=0] += 512*bq
__global__ void k_mix(const float* __restrict__ fwr,
                      const float* __restrict__ fwi,
                      const float* __restrict__ bq, int layer) {
    int p = blockIdx.x * 4 + (threadIdx.x >> 6);
    int m = threadIdx.x & 63;
    int b = p >> 3, hh = p & 7;
    const float* wr = fwr + (size_t)((layer*H_ + hh)*E_*E_) * 64;
    const float* wi = fwi + (size_t)((layer*H_ + hh)*E_*E_) * 64;
    float sr[E_], si[E_];
    #pragma unroll
    for (int o = 0; o < E_; o++) { sr[o] = 0.f; si[o] = 0.f; }
    const float* Fb = g_F + (b*128 + hh*16) * 128;
    const float* bql = bq + layer*128 + hh*16;
    #pragma unroll
    for (int e = 0; e < E_; e++) {
        float fre = Fb[e*128 + m];
        if (m == 0) fre += 512.0f * bql[e];
        float fim = Fb[e*128 + 64 + m];
        #pragma unroll
        for (int o = 0; o < E_; o++) {
            float cr = wr[(e*E_ + o)*64 + m];
            float ci = wi[(e*E_ + o)*64 + m];
            sr[o] += fre*cr - fim*ci;
            si[o] += fre*ci + fim*cr;
        }
    }
    int base = (b*128 + hh*16) * 128;
    #pragma unroll
    for (int o = 0; o < E_; o++) {
        g_S[base + o*128 + m]      = __float2half_rn(sr[o]);
        g_S[base + o*128 + 64 + m] = __float2half_rn(si[o]);
    }
}

// ---------------- series_decomp: fp32 in, fp16 out (flat only) -------------
__global__ void k_movsub(const float* __restrict__ X, __half* __restrict__ Oh) {
    __shared__ float sh[88 * 128];
    int b = blockIdx.x, t0 = blockIdx.y * 64;
    int d = threadIdx.x;
    const float* Xb = X + b*65536;
    #pragma unroll 4
    for (int r = 0; r < 88; r++) {
        int t = t0 + r - 12;
        t = max(0, min(511, t));
        sh[r*128 + d] = Xb[t*128 + d];
    }
    float s = 0.f;
    #pragma unroll 4
    for (int r = 0; r < 88; r++) { s += sh[r*128 + d]; sh[r*128 + d] = s; }
    #pragma unroll 4
    for (int tt = 0; tt < 64; tt++) {
        int r = tt + 12;
        float hi = sh[(r+12)*128 + d];
        float lo = (r >= 13) ? sh[(r-13)*128 + d] : 0.f;
        float v = Xb[(t0+tt)*128 + d] - (hi - lo) * (1.0f/25.0f);
        Oh[b*65536 + (t0+tt)*128 + d] = __float2half_rn(v);
    }
}

// ---------------- series_decomp writing flat + transposed HT ---------------
// dyn smem: 88*128 fp32 cumsum + 128*72 fp16 transpose tile = 63488 B
__global__ void k_movsubT(const float* __restrict__ X, __half* __restrict__ Oh) {
    extern __shared__ float dsm2[];
    float* sh = dsm2;
    __half* ts = (__half*)(dsm2 + 88*128);
    int b = blockIdx.x, t0 = blockIdx.y * 64;
    int d = threadIdx.x;
    const float* Xb = X + b*65536;
    #pragma unroll 4
    for (int r = 0; r < 88; r++) {
        int t = t0 + r - 12;
        t = max(0, min(511, t));
        sh[r*128 + d] = Xb[t*128 + d];
    }
    float s = 0.f;
    #pragma unroll 4
    for (int r = 0; r < 88; r++) { s += sh[r*128 + d]; sh[r*128 + d] = s; }
    #pragma unroll 4
    for (int tt = 0; tt < 64; tt++) {
        int r = tt + 12;
        float hi = sh[(r+12)*128 + d];
        float lo = (r >= 13) ? sh[(r-13)*128 + d] : 0.f;
        float v = Xb[(t0+tt)*128 + d] - (hi - lo) * (1.0f/25.0f);
        __half h = __float2half_rn(v);
        Oh[b*65536 + (t0+tt)*128 + d] = h;
        ts[d*72 + tt] = h;
    }
    __syncthreads();
    const __half* tsr = ts + d*72;
    __half* dst = g_HT + b*65536 + d*512 + t0;
    #pragma unroll
    for (int j = 0; j < 8; j++)
        *(uint4*)(dst + j*8) = *(const uint4*)(tsr + j*8);
}

// ---------------- fused decomp2 + LayerNorm + colmean (final layer) --------
__global__ void k_msln(const float* __restrict__ X, const float* __restrict__ g,
                       const float* __restrict__ be, __half* __restrict__ Out) {
    extern __shared__ float dsm[];
    float* sh = dsm;
    float* s2 = dsm + 88*128;
    float* cm = dsm + 96*128;
    int b = blockIdx.x, t0 = blockIdx.y * 64;
    int d = threadIdx.x;
    int wid = d >> 5, lane = d & 31;
    const float* Xb = X + b*65536;
    #pragma unroll 4
    for (int r = 0; r < 88; r++) {
        int t = t0 + r - 12;
        t = max(0, min(511, t));
        sh[r*128 + d] = Xb[t*128 + d];
    }
    float s = 0.f;
    #pragma unroll 4
    for (int r = 0; r < 88; r++) { s += sh[r*128 + d]; sh[r*128 + d] = s; }
    cm[d] = 0.f;
    __syncthreads();

    for (int gix = 0; gix < 8; gix++) {
        #pragma unroll
        for (int k = 0; k < 8; k++) {
            int tt = gix*8 + k, r = tt + 12;
            float hi = sh[(r+12)*128 + d];
            float lo = (r >= 13) ? sh[(r-13)*128 + d] : 0.f;
            s2[k*128 + d] = Xb[(t0+tt)*128 + d] - (hi - lo) * (1.0f/25.0f);
        }
        __syncthreads();
        #pragma unroll
        for (int rr = 0; rr < 2; rr++) {
            int k = wid*2 + rr;
            int trow = t0 + gix*8 + k;
            float v[4];
            float su = 0.f;
            #pragma unroll
            for (int i = 0; i < 4; i++) { v[i] = s2[k*128 + lane + i*32]; su += v[i]; }
            #pragma unroll
            for (int o = 16; o > 0; o >>= 1) su += __shfl_xor_sync(0xffffffffu, su, o);
            float mu = su * (1.0f/128.0f);
            float q = 0.f;
            #pragma unroll
            for (int i = 0; i < 4; i++) { float dl = v[i] - mu; q += dl*dl; }
            #pragma unroll
            for (int o = 16; o > 0; o >>= 1) q += __shfl_xor_sync(0xffffffffu, q, o);
            float rstd = rsqrtf(q * (1.0f/128.0f) + 1e-5f);
            __half* orow = Out + (size_t)(b*512 + trow) * 128;
            #pragma unroll
            for (int i = 0; i < 4; i++) {
                int dd = lane + i*32;
                float o = (v[i] - mu) * rstd * g[dd] + be[dd];
                orow[dd] = __float2half_rn(o);
                atomicAdd(&cm[dd], o);
            }
        }
        __syncthreads();
    }
    atomicAdd(&g_CM[b*128 + d], cm[d]);
}

// ---------------- final ----------------
__global__ void k_final(const __half* __restrict__ HN, const float* __restrict__ pw,
                        float* __restrict__ out) {
    int b = blockIdx.x, tid = threadIdx.x;
    int loc0 = blockIdx.y*8192;
    int base = b*65536 + loc0;
    float s = 0.f;
    for (int i = tid*2; i < 8192; i += 512) {
        int gi = base + i;
        __half2 h  = *(const __half2*)(HN + gi);
        __half2 mk = *(const __half2*)(g_MarkH + gi);
        float2 pp  = *(const float2*)(pw + loc0 + i);
        int dbase = b*128 + (gi & 127);
        float v0 = __low2float(h)  - g_CM[dbase]     * (1.0f/512.0f);
        float v1 = __high2float(h) - g_CM[dbase + 1] * (1.0f/512.0f);
        s += geluf(v0) * __low2float(mk)  * pp.x;
        s += geluf(v1) * __high2float(mk) * pp.y;
    }
    __shared__ float red[256];
    red[tid] = s; __syncthreads();
    #pragma unroll
    for (int o = 128; o > 0; o >>= 1) {
        if (tid < o) red[tid] += red[tid + o];
        __syncthreads();
    }
    if (tid == 0) atomicAdd(&out[b], red[0]);
}

// ---------------- host orchestration ----------------
#define SMB    49152
#define SMLN   49664
#define SMMT   63488

extern "C" void kernel_launch(void* const* d_in, const int* in_sizes, int n_in,
                              void* d_out, int out_size) {
    const float* x_enc  = (const float*)d_in[0];
    const float* mark   = (const float*)d_in[1];
    const float* conv_w = (const float*)d_in[4];
    const float* Wq     = (const float*)d_in[5];
    const float* bq     = (const float*)d_in[6];
    const float* Wo     = (const float*)d_in[7];
    const float* bo     = (const float*)d_in[8];
    const float* fwr    = (const float*)d_in[9];
    const float* fwi    = (const float*)d_in[10];
    const float* W1     = (const float*)d_in[11];
    const float* W2     = (const float*)d_in[12];
    const float* ln_g   = (const float*)d_in[13];
    const float* ln_b   = (const float*)d_in[14];
    const float* pw     = (const float*)d_in[15];
    const float* pb     = (const float*)d_in[16];
    float* out = (float*)d_out;

    cudaFuncSetAttribute(k_tgemm<24,1,1>, cudaFuncAttributeMaxDynamicSharedMemorySize, SMB);
    cudaFuncSetAttribute(k_tgemm<16,0,3>, cudaFuncAttributeMaxDynamicSharedMemorySize, SMB);
    cudaFuncSetAttribute(k_tgemm<16,0,2>, cudaFuncAttributeMaxDynamicSharedMemorySize, SMB);
    cudaFuncSetAttribute(k_tgemm<16,1,0>, cudaFuncAttributeMaxDynamicSharedMemorySize, SMB);
    cudaFuncSetAttribute(k_tgemm<3,0,0>,  cudaFuncAttributeMaxDynamicSharedMemorySize, SMB);
    cudaFuncSetAttribute(k_tgemm<20,1,0>, cudaFuncAttributeMaxDynamicSharedMemorySize, SMB);
    cudaFuncSetAttribute(k_tgemm<2,0,0>,  cudaFuncAttributeMaxDynamicSharedMemorySize, SMB);
    cudaFuncSetAttribute(k_msln,    cudaFuncAttributeMaxDynamicSharedMemorySize, SMLN);
    cudaFuncSetAttribute(k_movsubT, cudaFuncAttributeMaxDynamicSharedMemorySize, SMMT);

    float *pT2, *pF;
    cudaGetSymbolAddress((void**)&pT2,  g_T2);
    cudaGetSymbolAddress((void**)&pF,   g_F);
    __half *x16,*hx,*ht,*gt,*q16,*s16,*u16,*hn;
    cudaGetSymbolAddress((void**)&x16, g_X);
    cudaGetSymbolAddress((void**)&hx,  g_Hx);
    cudaGetSymbolAddress((void**)&ht,  g_HT);
    cudaGetSymbolAddress((void**)&gt,  g_GT);
    cudaGetSymbolAddress((void**)&q16, g_Q);
    cudaGetSymbolAddress((void**)&s16, g_S);
    cudaGetSymbolAddress((void**)&u16, g_U);
    cudaGetSymbolAddress((void**)&hn,  g_HN);
    __half *cw,*fb,*ib,*wq,*wo,*w1,*w2;
    cudaGetSymbolAddress((void**)&cw, g_cw);
    cudaGetSymbolAddress((void**)&fb, g_fb);
    cudaGetSymbolAddress((void**)&ib, g_ib);
    cudaGetSymbolAddress((void**)&wq, g_wq);
    cudaGetSymbolAddress((void**)&wo, g_wo);
    cudaGetSymbolAddress((void**)&w1, g_w1);
    cudaGetSymbolAddress((void**)&w2, g_w2);

    k_prep<<<256, 256>>>(conv_w, Wq, Wo, W1, W2, pb, out);
    k_transpose<<<dim3(16,4,128), dim3(32,8)>>>(x_enc, mark);

    // TokenEmbedding conv (K=384) + PE -> fp16 H (flat) + HT (b,d,l)
    k_tgemm<24,1,1><<<dim3(1024,1), 256, SMB>>>(
        x16, cw, nullptr, nullptr, nullptr, hx, ht,
        384, 128, 9, LP_*128, 128);

    for (int l = 0; l < 2; l++) {
        // forward DFT of H -> GT [(b,n),k] fp16
        k_tgemm<16,0,3><<<dim3(256,1), 256, SMB>>>(
            ht, fb, nullptr, nullptr, nullptr, nullptr, gt,
            512, 128, 30, 0, 512);
        // freq-domain Wq: F[(b,he),n] fp32 (transposed write)
        k_tgemm<16,0,2><<<dim3(256,1), 256, SMB>>>(
            gt, wq + l*16384, nullptr, nullptr, pF, nullptr, nullptr,
            128, 128, 30, 0, 128);
        // complex mode mixing (+512*bq at mode 0) -> fp16 S
        k_mix<<<256, 256>>>(fwr, fwi, bq, l);
        // inverse DFT -> fp16 flat (== scrambled view(B,L,-1))
        k_tgemm<16,1,0><<<dim3(256,4), 256, SMB>>>(
            s16, ib, nullptr, nullptr, nullptr, q16, nullptr,
            128, 512, 30, 0, 128);
        // out proj + bias + residual(fp16 H) -> fp32 T2
        k_tgemm<3,0,0><<<dim3(1024,1), 256, SMB>>>(
            q16, wo + l*16384, bo + l*128, hx, pT2, nullptr, nullptr,
            128, 128, 30, 0, 128);
        // decomp1 -> fp16 H flat
        k_movsub<<<dim3(128,8), 128>>>(pT2, hx);
        // FFN up + gelu -> fp16 U
        k_tgemm<20,1,0><<<dim3(1024,4), 256, SMB>>>(
            hx, w1 + l*65536, nullptr, nullptr, nullptr, u16, nullptr,
            128, 512, 30, 0, 128);
        // FFN down + residual(fp16 H) -> fp32 T2
        k_tgemm<2,0,0><<<dim3(1024,1), 256, SMB>>>(
            u16, w2 + l*65536, nullptr, hx, pT2, nullptr, nullptr,
            512, 128, 30, 0, 512);
        // decomp2
        if (l == 0) {
            k_movsubT<<<dim3(128,8), 128, SMMT>>>(pT2, hx);   // flat + HT
        } else {
            k_msln<<<dim3(128,8), 128, SMLN>>>(pT2, ln_g, ln_b, hn);
        }
    }

    k_final<<<dim3(128,8), 256>>>(hn, pw, out);
}

// round 16
// speedup vs baseline: 1.0920x; 1.0920x over previous
#include <cuda_runtime.h>
#include <cuda_fp16.h>
#include <math.h>
#include <stdint.h>

#define B_    128
#define L_    512
#define D_    128
#define H_    8
#define E_    16
#define DFF_  512
#define LP_   514

// ---------------- fp32 scratch ----------------
__device__ float g_T2 [B_*L_*D_];
__device__ float g_F  [B_*D_*128];
__device__ float g_PE [512*128];
__device__ float g_CM [B_*D_];

// ---------------- fp16 scratch ----------------
__device__ __half g_MarkH[B_*L_*D_];
__device__ __half g_X [B_*LP_*D_];
__device__ __half g_Hx[B_*L_*D_];
__device__ __half g_Q [B_*L_*D_];
__device__ __half g_QT[B_*L_*D_];
__device__ __half g_S [B_*D_*128];
__device__ __half g_U [B_*L_*DFF_];
__device__ __half g_HN[B_*L_*D_];

// ---------------- fp16 weights ----------------
__device__ __half g_cw[128*384];
__device__ __half g_fb[128*512];
__device__ __half g_ib[512*128];
__device__ __half g_wq[2*128*128];
__device__ __half g_wo[2*128*128];
__device__ __half g_w1[2*512*128];
__device__ __half g_w2[2*128*512];

__device__ __forceinline__ float geluf(float v) {
    return 0.5f * v * (1.0f + erff(v * 0.7071067811865476f));
}
__device__ __forceinline__ uint32_t pack2h(__half a, __half b) {
    return (uint32_t)__half_as_ushort(a) | ((uint32_t)__half_as_ushort(b) << 16);
}
__device__ __forceinline__ uint32_t smem_u32(const void* p) {
    uint32_t a;
    asm("{ .reg .u64 t; cvta.to.shared.u64 t, %1; cvt.u32.u64 %0, t; }" : "=r"(a) : "l"(p));
    return a;
}
__device__ __forceinline__ void ldsm4(uint32_t* r, uint32_t a) {
    asm volatile("ldmatrix.sync.aligned.m8n8.x4.shared.b16 {%0,%1,%2,%3}, [%4];"
        : "=r"(r[0]), "=r"(r[1]), "=r"(r[2]), "=r"(r[3]) : "r"(a));
}
__device__ __forceinline__ void mma16816(float* c, const uint32_t* a, const uint32_t* b) {
    asm volatile(
        "mma.sync.aligned.m16n8k16.row.col.f32.f16.f16.f32 "
        "{%0,%1,%2,%3}, {%4,%5,%6,%7}, {%8,%9}, {%0,%1,%2,%3};"
        : "+f"(c[0]), "+f"(c[1]), "+f"(c[2]), "+f"(c[3])
        : "r"(a[0]), "r"(a[1]), "r"(a[2]), "r"(a[3]), "r"(b[0]), "r"(b[1]));
}
#define CP16(d, s)   asm volatile("cp.async.cg.shared.global [%0], [%1], 16;" :: "r"(d), "l"(s))
#define CPCOMMIT()   asm volatile("cp.async.commit_group;" ::: "memory")
#define CPWAIT2()    asm volatile("cp.async.wait_group 2;" ::: "memory")

__device__ __forceinline__ uint32_t sw32(int row, int ch) {
    return (uint32_t)(row * 64) + (uint32_t)(((ch ^ ((row >> 1) & 3)) << 4));
}

// ---------------- prep: weights -> fp16 [N,K]; PE; zero CM; out=pb ---------
__global__ void k_prep(const float* __restrict__ conv_w, const float* __restrict__ Wq,
                       const float* __restrict__ Wo, const float* __restrict__ W1,
                       const float* __restrict__ W2, const float* __restrict__ pb,
                       float* __restrict__ out) {
    int idx = blockIdx.x * 256 + threadIdx.x;   // 65536 total
    if (idx < 49152) {
        int n = idx / 384, k = idx - n*384;
        int s = k >> 7, din = k & 127;
        g_cw[idx] = __float2half_rn(conv_w[n*384 + din*3 + s]);
    }
    if (idx < B_*D_) g_CM[idx] = 0.f;
    if (idx < B_)    out[idx] = pb[0];
    {   // forward DFT basis: N=128 (coeff), K=512 (t)
        int n = idx >> 9, t = idx & 511, m = n & 63;
        float x = (float)(m * t) * (1.0f/256.0f);
        float v = (n < 64) ? cospif(x) : -sinpif(x);
        g_fb[idx] = __float2half_rn(v);
    }
    {   // inverse DFT basis: N=512 (t), K=128 (coeff)
        int t = idx >> 7, n = idx & 127, m = n & 63;
        float x = (float)(m * t) * (1.0f/256.0f);
        float v;
        if (n == 0)       v = 1.0f/512.0f;
        else if (n < 64)  v = cospif(x) * (2.0f/512.0f);
        else if (n == 64) v = 0.0f;
        else              v = -sinpif(x) * (2.0f/512.0f);
        g_ib[idx] = __float2half_rn(v);
    }
    #pragma unroll
    for (int ly = 0; ly < 2; ly++) {
        if (idx < 16384) {
            int n = idx >> 7, k = idx & 127;
            g_wq[ly*16384 + idx] = __float2half_rn(Wq[ly*16384 + k*128 + n]);
            g_wo[ly*16384 + idx] = __float2half_rn(Wo[ly*16384 + k*128 + n]);
        }
        {
            int n = idx >> 7, k = idx & 127;
            g_w1[ly*65536 + idx] = __float2half_rn(W1[ly*65536 + k*512 + n]);
        }
        {
            int n = idx >> 9, k = idx & 511;
            g_w2[ly*65536 + idx] = __float2half_rn(W2[ly*65536 + k*128 + n]);
        }
    }
    {
        int t = idx >> 7, d = idx & 127;
        int i2 = d & ~1;
        float div = expf((float)i2 * (-9.210340371976184f / 128.0f));
        float a = (float)t * div;
        g_PE[idx] = (d & 1) ? cosf(a) : sinf(a);
    }
}

// ---------------- input transpose + circular edges (fused) -----------------
__global__ void k_transpose(const float* __restrict__ x_enc,
                            const float* __restrict__ mark) {
    __shared__ float tile [32][33];
    __shared__ float tileM[32][33];
    int b = blockIdx.z;
    int d0 = blockIdx.y * 32, l0 = blockIdx.x * 32;
    int tx = threadIdx.x, ty = threadIdx.y;
    const float* xb = x_enc + b*65536;
    const float* mb = mark  + b*65536;
    #pragma unroll
    for (int i = ty; i < 32; i += 8) {
        tile [i][tx] = xb[(d0+i)*512 + l0 + tx];
        tileM[i][tx] = mb[(d0+i)*512 + l0 + tx];
    }
    __syncthreads();
    #pragma unroll
    for (int i = ty; i < 32; i += 8) {
        int oi = b*LP_*128 + (l0+i+1)*128 + d0+tx;
        g_X[oi] = __float2half_rn(tile[tx][i]);
        g_MarkH[b*65536 + (l0+i)*128 + d0+tx] = __float2half_rn(tileM[tx][i]);
    }
    if (ty == 0) {
        if (blockIdx.x == 0)
            g_X[b*LP_*128 + 513*128 + d0+tx] = __float2half_rn(tile[tx][0]);
        if (blockIdx.x == 15)
            g_X[b*LP_*128 + d0+tx] = __float2half_rn(tile[tx][31]);
    }
}

// ---------------- fp16 HMMA GEMM, cp.async 4-stage, K-chunk 32 --------------
// CTA tile 64(M) x 128(N); 8 warps of 32x32; 4 CTAs/SM.
// EPI bits: 1=+bias[col], 2=+res(fp16), 4=gelu, 8=+PE, 16=skip fp32 C store
// WRB: write fp16 result to Cf (flat).  WRT: smem-staged transposed write to g_QT.
template<int EPI, int WRB, int WRT>
__global__ void __launch_bounds__(256, 4) k_tgemm(
    const __half* __restrict__ A, const __half* __restrict__ B,
    const float* __restrict__ bias, const __half* __restrict__ res,
    float* __restrict__ C, __half* __restrict__ Cf,
    int K, int ldc, int absh, int abstr, int arstr)
{
    extern __shared__ char sm[];
    const uint32_t sU = smem_u32(sm);
    const int tid = threadIdx.x, wid = tid >> 5, lane = tid & 31;
    const int rowBase = blockIdx.x * 64, colBase = blockIdx.y * 128;
    const int amask = (1 << absh) - 1;

    float acc[2][4][4];
    #pragma unroll
    for (int i = 0; i < 2; i++)
        #pragma unroll
        for (int j = 0; j < 4; j++)
            #pragma unroll
            for (int q = 0; q < 4; q++) acc[i][j][q] = 0.f;

    const int nc = K >> 5;

    const int a_row = tid >> 2, a_ch = tid & 3;
    const uint32_t a_sw = sw32(a_row, a_ch);
    int a_rg = rowBase + a_row;
    const long a_base = (long)(a_rg >> absh)*abstr + (long)(a_rg & amask)*arstr + a_ch*8;
    const int b_row0 = tid >> 2, b_row1 = 64 + (tid >> 2);
    const uint32_t b_sw0 = sw32(b_row0, a_ch), b_sw1 = sw32(b_row1, a_ch);
    const long b_base0 = (long)(colBase + b_row0)*K + a_ch*8;
    const long b_base1 = (long)(colBase + b_row1)*K + a_ch*8;

    auto load_chunk = [&](int stage, int k0) {
        uint32_t sb = sU + stage * 12288;
        CP16(sb +        a_sw, A + a_base + k0);
        CP16(sb + 4096 + b_sw0, B + b_base0 + k0);
        CP16(sb + 4096 + b_sw1, B + b_base1 + k0);
    };

    load_chunk(0, 0);  CPCOMMIT();
    load_chunk(1, 32); CPCOMMIT();
    load_chunk(2, 64); CPCOMMIT();

    const int mrow = (wid & 1) * 32;
    const int ncol = (wid >> 1) * 32;
    const int a_lr  = mrow + (lane & 15);
    const int a_lc  = lane >> 4;
    const int b_lr  = ncol + (lane & 7) + ((lane & 16) ? 8 : 0);
    const int b_lc  = (lane >> 3) & 1;
    int stage = 0;

    for (int c = 0; c < nc; c++) {
        CPWAIT2();
        __syncthreads();
        if (c + 3 < nc) load_chunk((stage + 3) & 3, (c + 3) * 32);
        CPCOMMIT();

        uint32_t sb = sU + stage * 12288;
        #pragma unroll
        for (int ks = 0; ks < 2; ks++) {
            uint32_t af[2][4], bf[2][4];
            #pragma unroll
            for (int g = 0; g < 2; g++) {
                int r = b_lr + g*16, ci = ks*2 + b_lc;
                ldsm4(bf[g], sb + 4096 + sw32(r, ci));
            }
            #pragma unroll
            for (int f = 0; f < 2; f++) {
                int r = a_lr + f*16, ci = ks*2 + a_lc;
                ldsm4(af[f], sb + sw32(r, ci));
            }
            #pragma unroll
            for (int mi = 0; mi < 2; mi++)
                #pragma unroll
                for (int ni = 0; ni < 4; ni++)
                    mma16816(acc[mi][ni], af[mi], &bf[ni >> 1][(ni & 1) * 2]);
        }
        stage = (stage + 1) & 3;
    }

    if (WRT) __syncthreads();   // reclaim pipeline smem for transpose staging
    __half* tst = (__half*)(sm + wid * 2176);   // 32x33 halves per warp

    // ---- epilogue ----
    #pragma unroll
    for (int mi = 0; mi < 2; mi++) {
        #pragma unroll
        for (int half = 0; half < 2; half++) {
            int grow = rowBase + mrow + mi*16 + (lane >> 2) + half*8;
            #pragma unroll
            for (int ni = 0; ni < 4; ni++) {
                int gcol = colBase + ncol + ni*8 + (lane & 3)*2;
                float v0 = acc[mi][ni][half*2 + 0];
                float v1 = acc[mi][ni][half*2 + 1];
                if (EPI & 1) { v0 += bias[gcol]; v1 += bias[gcol + 1]; }
                if (EPI & 8) {
                    int pbi = (grow & 511)*128 + (gcol & 127);
                    v0 += g_PE[pbi]; v1 += g_PE[pbi + 1];
                }
                long oidx = (long)grow * ldc + gcol;
                if (EPI & 2) {
                    __half2 rr = *(const __half2*)(res + oidx);
                    v0 += __low2float(rr); v1 += __high2float(rr);
                }
                if (EPI & 4) { v0 = geluf(v0); v1 = geluf(v1); }
                if (!(EPI & 16)) {
                    float2 o; o.x = v0; o.y = v1;
                    *(float2*)(C + oidx) = o;
                }
                if (WRB) {
                    *(uint32_t*)(Cf + oidx) =
                        pack2h(__float2half_rn(v0), __float2half_rn(v1));
                }
                if (WRT) {
                    int cl = ni*8 + (lane & 3)*2;
                    int rl = mi*16 + (lane >> 2) + half*8;
                    tst[cl*33 + rl]     = __float2half_rn(v0);
                    tst[(cl+1)*33 + rl] = __float2half_rn(v1);
                }
            }
        }
    }
    if (WRT) {
        __syncwarp();
        int bI = rowBase >> 9;
        int tb = (rowBase & 511) + mrow + (lane & 7)*4;
        #pragma unroll
        for (int rep = 0; rep < 8; rep++) {
            int dl = rep*4 + (lane >> 3);
            int tl = (lane & 7)*4;
            __half h0 = tst[dl*33 + tl],     h1 = tst[dl*33 + tl + 1];
            __half h2 = tst[dl*33 + tl + 2], h3 = tst[dl*33 + tl + 3];
            uint2 o; o.x = pack2h(h0, h1); o.y = pack2h(h2, h3);
            int dg = (colBase + ncol + dl) & 127;
            *(uint2*)(g_QT + bI*65536 + dg*512 + tb) = o;
        }
    }
}

// ---------------- complex mode mixing (fp32 in, fp16 out) ------------------
__global__ void k_mix(const float* __restrict__ fwr,
                      const float* __restrict__ fwi, int layer) {
    int p = blockIdx.x * 4 + (threadIdx.x >> 6);
    int m = threadIdx.x & 63;
    int b = p >> 3, hh = p & 7;
    const float* wr = fwr + (size_t)((layer*H_ + hh)*E_*E_) * 64;
    const float* wi = fwi + (size_t)((layer*H_ + hh)*E_*E_) * 64;
    float sr[E_], si[E_];
    #pragma unroll
    for (int o = 0; o < E_; o++) { sr[o] = 0.f; si[o] = 0.f; }
    const float* Fb = g_F + (b*128 + hh*16) * 128;
    #pragma unroll
    for (int e = 0; e < E_; e++) {
        float fre = Fb[e*128 + m];
        float fim = Fb[e*128 + 64 + m];
        #pragma unroll
        for (int o = 0; o < E_; o++) {
            float cr = wr[(e*E_ + o)*64 + m];
            float ci = wi[(e*E_ + o)*64 + m];
            sr[o] += fre*cr - fim*ci;
            si[o] += fre*ci + fim*cr;
        }
    }
    int base = (b*128 + hh*16) * 128;
    #pragma unroll
    for (int o = 0; o < E_; o++) {
        g_S[base + o*128 + m]      = __float2half_rn(sr[o]);
        g_S[base + o*128 + 64 + m] = __float2half_rn(si[o]);
    }
}

// ---------------- series_decomp: fp32 in, fp16 out --------------------------
// original value recovered from cumsum: orig[r] = cs[r] - cs[r-1] (r >= 12)
__global__ void k_movsub(const float* __restrict__ X, __half* __restrict__ Oh) {
    __shared__ float sh[88 * 128];
    int b = blockIdx.x, t0 = blockIdx.y * 64;
    int d = threadIdx.x;
    const float* Xb = X + b*65536;
    #pragma unroll 4
    for (int r = 0; r < 88; r++) {
        int t = t0 + r - 12;
        t = max(0, min(511, t));
        sh[r*128 + d] = Xb[t*128 + d];
    }
    float s = 0.f;
    #pragma unroll 4
    for (int r = 0; r < 88; r++) { s += sh[r*128 + d]; sh[r*128 + d] = s; }
    #pragma unroll 4
    for (int tt = 0; tt < 64; tt++) {
        int r = tt + 12;
        float hi = sh[(r+12)*128 + d];
        float lo = (r >= 13) ? sh[(r-13)*128 + d] : 0.f;
        float orig = sh[r*128 + d] - sh[(r-1)*128 + d];
        float v = orig - (hi - lo) * (1.0f/25.0f);
        Oh[b*65536 + (t0+tt)*128 + d] = __float2half_rn(v);
    }
}

// ---------------- fused decomp2 + LayerNorm + colmean (final layer) --------
// dyn smem: cumsum 88*128 | seasonal 8*128 | cm 128  = 49664 B
__global__ void k_msln(const float* __restrict__ X, const float* __restrict__ g,
                       const float* __restrict__ be, __half* __restrict__ Out) {
    extern __shared__ float dsm[];
    float* sh = dsm;
    float* s2 = dsm + 88*128;
    float* cm = dsm + 96*128;
    int b = blockIdx.x, t0 = blockIdx.y * 64;
    int d = threadIdx.x;
    int wid = d >> 5, lane = d & 31;
    const float* Xb = X + b*65536;
    #pragma unroll 4
    for (int r = 0; r < 88; r++) {
        int t = t0 + r - 12;
        t = max(0, min(511, t));
        sh[r*128 + d] = Xb[t*128 + d];
    }
    float s = 0.f;
    #pragma unroll 4
    for (int r = 0; r < 88; r++) { s += sh[r*128 + d]; sh[r*128 + d] = s; }
    cm[d] = 0.f;
    __syncthreads();

    for (int gix = 0; gix < 8; gix++) {
        #pragma unroll
        for (int k = 0; k < 8; k++) {
            int tt = gix*8 + k, r = tt + 12;
            float hi = sh[(r+12)*128 + d];
            float lo = (r >= 13) ? sh[(r-13)*128 + d] : 0.f;
            float orig = sh[r*128 + d] - sh[(r-1)*128 + d];
            s2[k*128 + d] = orig - (hi - lo) * (1.0f/25.0f);
        }
        __syncthreads();
        #pragma unroll
        for (int rr = 0; rr < 2; rr++) {
            int k = wid*2 + rr;
            int trow = t0 + gix*8 + k;
            float v[4];
            float su = 0.f;
            #pragma unroll
            for (int i = 0; i < 4; i++) { v[i] = s2[k*128 + lane + i*32]; su += v[i]; }
            #pragma unroll
            for (int o = 16; o > 0; o >>= 1) su += __shfl_xor_sync(0xffffffffu, su, o);
            float mu = su * (1.0f/128.0f);
            float q = 0.f;
            #pragma unroll
            for (int i = 0; i < 4; i++) { float dl = v[i] - mu; q += dl*dl; }
            #pragma unroll
            for (int o = 16; o > 0; o >>= 1) q += __shfl_xor_sync(0xffffffffu, q, o);
            float rstd = rsqrtf(q * (1.0f/128.0f) + 1e-5f);
            __half* orow = Out + (size_t)(b*512 + trow) * 128;
            #pragma unroll
            for (int i = 0; i < 4; i++) {
                int dd = lane + i*32;
                float o = (v[i] - mu) * rstd * g[dd] + be[dd];
                orow[dd] = __float2half_rn(o);
                atomicAdd(&cm[dd], o);
            }
        }
        __syncthreads();
    }
    atomicAdd(&g_CM[b*128 + d], cm[d]);
}

// ---------------- final ----------------
__global__ void k_final(const __half* __restrict__ HN, const float* __restrict__ pw,
                        float* __restrict__ out) {
    int b = blockIdx.x, tid = threadIdx.x;
    int loc0 = blockIdx.y*8192;
    int base = b*65536 + loc0;
    float s = 0.f;
    for (int i = tid*2; i < 8192; i += 512) {
        int gi = base + i;
        __half2 h  = *(const __half2*)(HN + gi);
        __half2 mk = *(const __half2*)(g_MarkH + gi);
        float2 pp  = *(const float2*)(pw + loc0 + i);
        int dbase = b*128 + (gi & 127);
        float v0 = __low2float(h)  - g_CM[dbase]     * (1.0f/512.0f);
        float v1 = __high2float(h) - g_CM[dbase + 1] * (1.0f/512.0f);
        s += geluf(v0) * __low2float(mk)  * pp.x;
        s += geluf(v1) * __high2float(mk) * pp.y;
    }
    __shared__ float red[256];
    red[tid] = s; __syncthreads();
    #pragma unroll
    for (int o = 128; o > 0; o >>= 1) {
        if (tid < o) red[tid] += red[tid + o];
        __syncthreads();
    }
    if (tid == 0) atomicAdd(&out[b], red[0]);
}

// ---------------- host orchestration ----------------
#define SMB    49152
#define SMLN   49664

extern "C" void kernel_launch(void* const* d_in, const int* in_sizes, int n_in,
                              void* d_out, int out_size) {
    const float* x_enc  = (const float*)d_in[0];
    const float* mark   = (const float*)d_in[1];
    const float* conv_w = (const float*)d_in[4];
    const float* Wq     = (const float*)d_in[5];
    const float* bq     = (const float*)d_in[6];
    const float* Wo     = (const float*)d_in[7];
    const float* bo     = (const float*)d_in[8];
    const float* fwr    = (const float*)d_in[9];
    const float* fwi    = (const float*)d_in[10];
    const float* W1     = (const float*)d_in[11];
    const float* W2     = (const float*)d_in[12];
    const float* ln_g   = (const float*)d_in[13];
    const float* ln_b   = (const float*)d_in[14];
    const float* pw     = (const float*)d_in[15];
    const float* pb     = (const float*)d_in[16];
    float* out = (float*)d_out;

    cudaFuncSetAttribute(k_tgemm<24,1,0>, cudaFuncAttributeMaxDynamicSharedMemorySize, SMB);
    cudaFuncSetAttribute(k_tgemm<17,0,1>, cudaFuncAttributeMaxDynamicSharedMemorySize, SMB);
    cudaFuncSetAttribute(k_tgemm<0,0,0>,  cudaFuncAttributeMaxDynamicSharedMemorySize, SMB);
    cudaFuncSetAttribute(k_tgemm<16,1,0>, cudaFuncAttributeMaxDynamicSharedMemorySize, SMB);
    cudaFuncSetAttribute(k_tgemm<3,0,0>,  cudaFuncAttributeMaxDynamicSharedMemorySize, SMB);
    cudaFuncSetAttribute(k_tgemm<20,1,0>, cudaFuncAttributeMaxDynamicSharedMemorySize, SMB);
    cudaFuncSetAttribute(k_tgemm<2,0,0>,  cudaFuncAttributeMaxDynamicSharedMemorySize, SMB);
    cudaFuncSetAttribute(k_msln,          cudaFuncAttributeMaxDynamicSharedMemorySize, SMLN);

    float *pT2, *pF;
    cudaGetSymbolAddress((void**)&pT2,  g_T2);
    cudaGetSymbolAddress((void**)&pF,   g_F);
    __half *x16,*hx,*q16,*qt,*s16,*u16,*hn;
    cudaGetSymbolAddress((void**)&x16, g_X);
    cudaGetSymbolAddress((void**)&hx,  g_Hx);
    cudaGetSymbolAddress((void**)&q16, g_Q);
    cudaGetSymbolAddress((void**)&qt,  g_QT);
    cudaGetSymbolAddress((void**)&s16, g_S);
    cudaGetSymbolAddress((void**)&u16, g_U);
    cudaGetSymbolAddress((void**)&hn,  g_HN);
    __half *cw,*fb,*ib,*wq,*wo,*w1,*w2;
    cudaGetSymbolAddress((void**)&cw, g_cw);
    cudaGetSymbolAddress((void**)&fb, g_fb);
    cudaGetSymbolAddress((void**)&ib, g_ib);
    cudaGetSymbolAddress((void**)&wq, g_wq);
    cudaGetSymbolAddress((void**)&wo, g_wo);
    cudaGetSymbolAddress((void**)&w1, g_w1);
    cudaGetSymbolAddress((void**)&w2, g_w2);

    k_prep<<<256, 256>>>(conv_w, Wq, Wo, W1, W2, pb, out);
    k_transpose<<<dim3(16,4,128), dim3(32,8)>>>(x_enc, mark);

    // TokenEmbedding conv (K=384) + PE -> fp16 H
    k_tgemm<24,1,0><<<dim3(1024,1), 256, SMB>>>(
        x16, cw, nullptr, nullptr, nullptr, hx, 384, 128, 9, LP_*128, 128);

    for (int l = 0; l < 2; l++) {
        // Q = H @ Wq + bq -> transposed fp16 (b,d,l)
        k_tgemm<17,0,1><<<dim3(1024,1), 256, SMB>>>(
            hx, wq + l*16384, bq + l*128, nullptr, nullptr, nullptr,
            128, 128, 30, 0, 128);
        // forward DFT -> fp32 F
        k_tgemm<0,0,0><<<dim3(256,1), 256, SMB>>>(
            qt, fb, nullptr, nullptr, pF, nullptr, 512, 128, 30, 0, 512);
        // complex mode mixing -> fp16 S
        k_mix<<<256, 256>>>(fwr, fwi, l);
        // inverse DFT -> fp16 flat (== scrambled view(B,L,-1))
        k_tgemm<16,1,0><<<dim3(256,4), 256, SMB>>>(
            s16, ib, nullptr, nullptr, nullptr, q16, 128, 512, 30, 0, 128);
        // out proj + bias + residual(fp16 H) -> fp32 T2
        k_tgemm<3,0,0><<<dim3(1024,1), 256, SMB>>>(
            q16, wo + l*16384, bo + l*128, hx, pT2, nullptr,
            128, 128, 30, 0, 128);
        // decomp1 -> fp16 H
        k_movsub<<<dim3(128,8), 128>>>(pT2, hx);
        // FFN up + gelu -> fp16 U
        k_tgemm<20,1,0><<<dim3(1024,4), 256, SMB>>>(
            hx, w1 + l*65536, nullptr, nullptr, nullptr, u16,
            128, 512, 30, 0, 128);
        // FFN down + residual(fp16 H) -> fp32 T2
        k_tgemm<2,0,0><<<dim3(1024,1), 256, SMB>>>(
            u16, w2 + l*65536, nullptr, hx, pT2, nullptr,
            512, 128, 30, 0, 512);
        // decomp2
        if (l == 0) {
            k_movsub<<<dim3(128,8), 128>>>(pT2, hx);
        } else {
            k_msln<<<dim3(128,8), 128, SMLN>>>(pT2, ln_g, ln_b, hn);
        }
    }

    k_final<<<dim3(128,8), 256>>>(hn, pw, out);
}